// round 13
// baseline (speedup 1.0000x reference)
#include <cuda_runtime.h>
#include <cstdint>

// KV-cache scatter-copy via TMA 1D bulk copies (cp.async.bulk).
//   L=8, B=2, H=8, S_FULL=4096, S_NEW=4, D=128, fp32
// out (2,L,B,H,S_FULL,D) = stack(past_k, past_v) with a 4-row window per
// (l,b,h) overwritten from new_k/new_v at target_positions[b].
//
// R13 probe: present the DRAM controller with 32KB sequential bulk requests
// (instead of 32B LDG/STG sectors) to test whether the ~85%-of-spec plateau
// is read/write-turnaround loss that longer bursts can recover.
// Per tile (2048 float4, fully inside one (kv,l,b,h) slab):
//   bulk-load past -> SMEM, overlay window rows from new_k/new_v in SMEM,
//   fence async proxy, bulk-store SMEM -> out.

static constexpr unsigned D4       = 32;                       // float4 per row
static constexpr unsigned S_FULL   = 4096;
static constexpr unsigned S_NEW    = 4;
static constexpr unsigned H        = 8;
static constexpr unsigned B        = 2;
static constexpr unsigned L        = 8;
static constexpr unsigned PAST_F4  = L * B * H * S_FULL * D4;  // 2^24
static constexpr unsigned TOTAL_F4 = 2u * PAST_F4;             // 2^25

static constexpr unsigned TPB       = 256;
static constexpr unsigned TILE_F4   = 2048;                    // 32KB tile, 64 s-rows
static constexpr unsigned TILE_BYTES= TILE_F4 * 16;
static constexpr unsigned TILE_ROWS = TILE_F4 / D4;            // 64

__device__ __forceinline__ uint32_t smem_u32(const void* p) {
    uint32_t a;
    asm("{ .reg .u64 t; cvta.to.shared.u64 t, %1; cvt.u32.u64 %0, t; }"
        : "=r"(a) : "l"(p));
    return a;
}

__global__ void __launch_bounds__(TPB) kv_scatter_copy_bulk(
    const float4* __restrict__ pk,
    const float4* __restrict__ pv,
    const float4* __restrict__ nk,
    const float4* __restrict__ nv,
    const int*    __restrict__ tpos,
    float4*       __restrict__ out)
{
    __shared__ alignas(128) float4 buf[TILE_F4];
    __shared__ alignas(8)  uint64_t mbar;

    const unsigned tid  = threadIdx.x;
    const unsigned base = blockIdx.x * TILE_F4;          // tile-aligned float4 index

    // Tile is entirely within one (kv,l,b,h): decode from base.
    const unsigned r  = base >> 17;
    const unsigned h  = r & (H - 1);
    const unsigned b  = (r >> 3) & (B - 1);
    const unsigned l  = (r >> 4) & (L - 1);
    const unsigned kv = r >> 7;
    const unsigned s0 = (base >> 5) & (S_FULL - 1);      // first s-row of tile

    const uint32_t buf_sa  = smem_u32(buf);
    const uint32_t mbar_sa = smem_u32(&mbar);

    if (tid == 0) {
        asm volatile("mbarrier.init.shared.b64 [%0], 1;" :: "r"(mbar_sa) : "memory");
    }
    __syncthreads();

    if (tid == 0) {
        asm volatile("mbarrier.arrive.expect_tx.shared.b64 _, [%0], %1;"
                     :: "r"(mbar_sa), "r"(TILE_BYTES) : "memory");
        const float4* src = (kv ? pv : pk) + (base & (PAST_F4 - 1));
        asm volatile(
            "cp.async.bulk.shared::cta.global.mbarrier::complete_tx::bytes "
            "[%0], [%1], %2, [%3];"
            :: "r"(buf_sa), "l"(src), "r"(TILE_BYTES), "r"(mbar_sa)
            : "memory");
    }

    // Wait (acquire) for the bulk load.
    {
        uint32_t done;
        asm volatile(
            "{\n\t.reg .pred p;\n\t"
            "mbarrier.try_wait.parity.acquire.cta.shared::cta.b64 p, [%1], 0;\n\t"
            "selp.b32 %0, 1, 0, p;\n\t}"
            : "=r"(done) : "r"(mbar_sa) : "memory");
        while (!done) {
            asm volatile(
                "{\n\t.reg .pred p;\n\t"
                "mbarrier.try_wait.parity.acquire.cta.shared::cta.b64 p, [%1], 0, 0x989680;\n\t"
                "selp.b32 %0, 1, 0, p;\n\t}"
                : "=r"(done) : "r"(mbar_sa) : "memory");
        }
    }

    // Overlay new-token window rows that fall inside this tile.
    // 128 threads: j = tid/32 (window row 0..3), d4 = tid%32.
    const unsigned off = (unsigned)__ldg(&tpos[b]);
    if (tid < S_NEW * D4) {
        const unsigned j   = tid >> 5;
        const unsigned d4  = tid & (D4 - 1);
        const unsigned row = off + j - s0;               // unsigned wrap
        if (row < TILE_ROWS) {
            const float4* nw = (kv ? nv : nk)
                               + (((l * B + b) * H + h) * S_NEW + j) * D4 + d4;
            buf[row * D4 + d4] = __ldg(nw);
        }
    }
    __syncthreads();
    asm volatile("fence.proxy.async.shared::cta;" ::: "memory");

    if (tid == 0) {
        asm volatile(
            "cp.async.bulk.global.shared::cta.bulk_group [%0], [%1], %2;"
            :: "l"(out + base), "r"(buf_sa), "r"(TILE_BYTES)
            : "memory");
        asm volatile("cp.async.bulk.commit_group;" ::: "memory");
        asm volatile("cp.async.bulk.wait_group 0;" ::: "memory");
    }
}

extern "C" void kernel_launch(void* const* d_in, const int* in_sizes, int n_in,
                              void* d_out, int out_size)
{
    const float4* pk = (const float4*)d_in[0];
    const float4* pv = (const float4*)d_in[1];
    const float4* nk = (const float4*)d_in[2];
    const float4* nv = (const float4*)d_in[3];
    const int*    tp = (const int*)d_in[4];
    float4*       out = (float4*)d_out;

    constexpr unsigned blocks = TOTAL_F4 / TILE_F4;      // 16384
    kv_scatter_copy_bulk<<<blocks, TPB>>>(pk, pv, nk, nv, tp, out);
}

// round 14
// speedup vs baseline: 1.0100x; 1.0100x over previous
#include <cuda_runtime.h>
#include <cstdint>

// FINAL (session answer): KV-cache scatter-copy, pure HBM streaming at the
// read/write-turnaround wall.
//
// Evidence (10 distinct implementations): LDG/STG family across MLP 1/4/8,
// split-batch, 128/256-bit, TPB 128/256/512, occ 50-83%, tile 16-64KB,
// cache policies -> 149.9-152.1us kernel / 84.5-85.7% DRAM. TMA
// cp.async.bulk (32KB bursts) -> 153.5us/83.6%. CE memcpy -> ~159us.
// Persistent grid -> 165us. Traffic is at the information floor
// (512MB R + 512MB W, single fused pass); ~6.8 TB/s = the HBM3e 1:1 R/W
// turnaround ceiling, invariant across every engine and geometry.
//
//   L=8, B=2, H=8, S_FULL=4096, S_NEW=4, D=128, fp32
// out (2,L,B,H,S_FULL,D) = stack(past_k, past_v) with a 4-row window per
// (l,b,h) overwritten from new_k/new_v at target_positions[b].
//
// Winning variant: TPB=128, 8x float4 per thread, front-batched loads
// (MLP_p1=8), .cs loads on read-once past data, .cs stores, block-uniform
// kv/l/b/h decode (TILE = 2^10 < 2^17 -> bits >=17 uniform per block).

static constexpr unsigned D4       = 32;                       // float4 per row
static constexpr unsigned S_FULL   = 4096;
static constexpr unsigned S_NEW    = 4;
static constexpr unsigned H        = 8;
static constexpr unsigned B        = 2;
static constexpr unsigned L        = 8;
static constexpr unsigned PAST_F4  = L * B * H * S_FULL * D4;  // 2^24
static constexpr unsigned TOTAL_F4 = 2u * PAST_F4;             // 2^25

static constexpr unsigned TPB  = 128;
static constexpr unsigned U    = 8;
static constexpr unsigned TILE = TPB * U;                      // 1024 float4 per block

__global__ void __launch_bounds__(TPB) kv_scatter_copy_final(
    const float4* __restrict__ pk,
    const float4* __restrict__ pv,
    const float4* __restrict__ nk,
    const float4* __restrict__ nv,
    const int*    __restrict__ tpos,
    float4*       __restrict__ out)
{
    const unsigned base = blockIdx.x * TILE + threadIdx.x;

    // Bits >= 17 (h|b|l|kv) are uniform across the whole block.
    const unsigned r  = base >> 17;
    const unsigned h  = r & (H - 1);
    const unsigned b  = (r >> 3) & (B - 1);
    const unsigned l  = (r >> 4) & (L - 1);
    const unsigned kv = r >> 7;

    const unsigned off = (unsigned)__ldg(&tpos[b]);

    const float4* __restrict__ past = kv ? pv : pk;     // same layout as out slab
    const float4* __restrict__ nw   = (kv ? nv : nk)
                                      + (((l * B + b) * H + h) * S_NEW) * D4;

    float4 v[U];
#pragma unroll
    for (unsigned u = 0; u < U; u++) {
        const unsigned i  = base + u * TPB;
        const unsigned s  = (i >> 5) & (S_FULL - 1);
        const unsigned d4 = i & (D4 - 1);
        const unsigned w  = s - off;                    // in-window iff < S_NEW (unsigned wrap)
        if (w < S_NEW) {
            v[u] = __ldg(nw + w * D4 + d4);             // tiny window: keep in L2
        } else {
            v[u] = __ldcs(past + (i & (PAST_F4 - 1)));  // read-once bulk: streaming
        }
    }
#pragma unroll
    for (unsigned u = 0; u < U; u++) {
        __stcs(&out[base + u * TPB], v[u]);             // streaming store
    }
}

extern "C" void kernel_launch(void* const* d_in, const int* in_sizes, int n_in,
                              void* d_out, int out_size)
{
    const float4* pk = (const float4*)d_in[0];
    const float4* pv = (const float4*)d_in[1];
    const float4* nk = (const float4*)d_in[2];
    const float4* nv = (const float4*)d_in[3];
    const int*    tp = (const int*)d_in[4];
    float4*       out = (float4*)d_out;

    constexpr unsigned blocks = TOTAL_F4 / TILE;        // 32768
    kv_scatter_copy_final<<<blocks, TPB>>>(pk, pv, nk, nv, tp, out);
}